// round 1
// baseline (speedup 1.0000x reference)
#include <cuda_runtime.h>
#include <cuda_bf16.h>
#include <cstdint>

// Problem constants
#define CCH 256
#define HH 336
#define WW 336
#define NROI 2000
#define POOLP 7
#define K1 (CCH * POOLP * POOLP)  // 12544
#define FF 256

// GEMM tiling
#define BM 128
#define BN 128
#define BK 16
#define KS1 16          // split-K for GEMM1: 12544/16 = 784 per slice
#define KLEN1 (K1 / KS1)
#define KS2 2           // split-K for GEMM2: 256/2 = 128
#define KLEN2 (FF / KS2)

// ---------------- static device scratch (no allocations allowed) --------------
__device__ float g_xscan[(size_t)HH * (WW + 1) * CCH];          // [y][x][c], x-prefix sums
__device__ float g_ii[(size_t)(HH + 1) * (WW + 1) * CCH];       // [y][x][c], full integral image
__device__ float g_pooled[(size_t)NROI * K1];                   // [roi][p][c]  (k' = p*256 + c)
__device__ float g_w1p[(size_t)K1 * FF];                        // w1 permuted: [p][c][f]
__device__ float g_part1[(size_t)KS1 * NROI * FF];              // split-K partials GEMM1
__device__ float g_h1[(size_t)NROI * FF];
__device__ float g_part2[(size_t)KS2 * NROI * FF];              // split-K partials GEMM2
__device__ float g_h2[(size_t)NROI * FF];

// ---------------- kernel 1: x-direction prefix scan + transpose ---------------
// grid (HH, CCH/32), block 1024 (32 warps). Warp w scans channel cg*32+w, row y.
__global__ void k_xscan(const float* __restrict__ f) {
    __shared__ float s[32][WW + 1];   // [c_local][x], stride 337 (odd*) -> conflict free
    int y = blockIdx.x;
    int cg = blockIdx.y;
    int w = threadIdx.x >> 5;
    int lane = threadIdx.x & 31;
    int c = cg * 32 + w;
    const float* row = f + (size_t)c * HH * WW + (size_t)y * WW;

    if (lane == 0) s[w][0] = 0.f;
    float running = 0.f;
#pragma unroll
    for (int chunk = 0; chunk < 11; chunk++) {
        int x = chunk * 32 + lane;
        float v = (x < WW) ? row[x] : 0.f;
#pragma unroll
        for (int off = 1; off < 32; off <<= 1) {
            float t = __shfl_up_sync(0xffffffffu, v, off);
            if (lane >= off) v += t;
        }
        float tot = __shfl_sync(0xffffffffu, v, 31);
        v += running;
        running += tot;
        if (x < WW) s[w][x + 1] = v;
    }
    __syncthreads();

    // coalesced write: consecutive threads -> consecutive channels
    size_t base = (size_t)y * (WW + 1) * CCH + cg * 32;
    for (int i = threadIdx.x; i < (WW + 1) * 32; i += 1024) {
        int x = i >> 5;
        int cl = i & 31;
        g_xscan[base + (size_t)x * CCH + cl] = s[cl][x];
    }
}

// ---------------- kernel 2: y-direction prefix sum --------------------------
// grid (WW+1), block 256 (=C). thread handles one (x, c) column. Coalesced in c.
__global__ void k_yscan() {
    int x = blockIdx.x;
    int c = threadIdx.x;
    size_t off = (size_t)x * CCH + c;
    const size_t rowstride = (size_t)(WW + 1) * CCH;
    float run = 0.f;
    g_ii[off] = 0.f;  // y = 0 row
#pragma unroll 4
    for (int y = 0; y < HH; y++) {
        run += g_xscan[(size_t)y * rowstride + off];
        g_ii[(size_t)(y + 1) * rowstride + off] = run;
    }
}

// ---------------- kernel 3: ROI pooling via integral image -------------------
// grid NROI, block 256 (=C). 4 gathers per bin, each 1KB contiguous across c.
__global__ void k_pool(const int* __restrict__ rois) {
    int roi = blockIdx.x;
    int c = threadIdx.x;
    int x1 = rois[roi * 4 + 0];
    int y1 = rois[roi * 4 + 1];
    int x2 = rois[roi * 4 + 2];
    int y2 = rois[roi * 4 + 3];
    int Ly = y2 - y1 + 1;
    int Lx = x2 - x1 + 1;
    const size_t rowstride = (size_t)(WW + 1) * CCH;
    size_t outbase = (size_t)roi * K1 + c;

#pragma unroll
    for (int p = 0; p < POOLP * POOLP; p++) {
        int py = p / POOLP;
        int px = p % POOLP;
        int ylo = y1 + (py * Ly) / POOLP;
        int yhi = y1 + ((py + 1) * Ly + POOLP - 1) / POOLP;
        int xlo = x1 + (px * Lx) / POOLP;
        int xhi = x1 + ((px + 1) * Lx + POOLP - 1) / POOLP;
        float s = g_ii[(size_t)yhi * rowstride + (size_t)xhi * CCH + c]
                - g_ii[(size_t)ylo * rowstride + (size_t)xhi * CCH + c]
                - g_ii[(size_t)yhi * rowstride + (size_t)xlo * CCH + c]
                + g_ii[(size_t)ylo * rowstride + (size_t)xlo * CCH + c];
        float inva = 1.f / (float)((yhi - ylo) * (xhi - xlo));
        g_pooled[outbase + (size_t)p * CCH] = s * inva;
    }
}

// ---------------- kernel 4: permute w1 [c*49+p][f] -> [p*256+c][f] -----------
__global__ void k_permw1(const float* __restrict__ w1) {
    int kp = blockIdx.x;        // k' in [0, 12544)
    int f = threadIdx.x;        // 256
    int p = kp / CCH;
    int c = kp % CCH;
    g_w1p[(size_t)kp * FF + f] = w1[((size_t)c * (POOLP * POOLP) + p) * FF + f];
}

// ---------------- kernel 5: fp32 tiled GEMM, split-K partials ----------------
// C_part[z][m][n] = A[m, kk0:kk0+klen] @ B[kk0:kk0+klen, n]
// 128x128x16 tile, 256 threads, 8x8 micro-tiles (split 2x2 of 4x4 to stay
// conflict-free with float4 smem loads).
__global__ __launch_bounds__(256, 2) void k_gemm(
    const float* __restrict__ A, const float* __restrict__ B,
    float* __restrict__ Cpart, int M, int N, int K, int klen) {
    __shared__ float As[BK][BM];
    __shared__ float Bs[BK][BN];
    int m0 = blockIdx.x * BM;
    int n0 = blockIdx.y * BN;
    int kk0 = blockIdx.z * klen;
    int tid = threadIdx.x;
    int tx = tid & 15;
    int ty = tid >> 4;
    int lr = tid >> 2, ls = tid & 3;     // A-load: rows lr, lr+64; float4 seg ls
    int lbk = tid >> 5, lbn = tid & 31;  // B-load: k-rows lbk, lbk+8; float4 seg lbn

    float acc[8][8];
#pragma unroll
    for (int i = 0; i < 8; i++)
#pragma unroll
        for (int j = 0; j < 8; j++) acc[i][j] = 0.f;

    float* Cp = Cpart + (size_t)blockIdx.z * M * N;

    for (int kb = 0; kb < klen; kb += BK) {
#pragma unroll
        for (int h = 0; h < 2; h++) {
            int r = lr + h * 64;
            int gm = m0 + r;
            float4 v = make_float4(0.f, 0.f, 0.f, 0.f);
            if (gm < M) v = *(const float4*)(A + (size_t)gm * K + kk0 + kb + ls * 4);
            As[ls * 4 + 0][r] = v.x;
            As[ls * 4 + 1][r] = v.y;
            As[ls * 4 + 2][r] = v.z;
            As[ls * 4 + 3][r] = v.w;
        }
#pragma unroll
        for (int h = 0; h < 2; h++) {
            int kr = lbk + h * 8;
            float4 v = *(const float4*)(B + (size_t)(kk0 + kb + kr) * N + n0 + lbn * 4);
            *(float4*)&Bs[kr][lbn * 4] = v;
        }
        __syncthreads();
#pragma unroll
        for (int kk = 0; kk < BK; kk++) {
            float a[8], b[8];
            *(float4*)&a[0] = *(const float4*)&As[kk][ty * 4];
            *(float4*)&a[4] = *(const float4*)&As[kk][64 + ty * 4];
            *(float4*)&b[0] = *(const float4*)&Bs[kk][tx * 4];
            *(float4*)&b[4] = *(const float4*)&Bs[kk][64 + tx * 4];
#pragma unroll
            for (int i = 0; i < 8; i++)
#pragma unroll
                for (int j = 0; j < 8; j++) acc[i][j] += a[i] * b[j];
        }
        __syncthreads();
    }

#pragma unroll
    for (int ih = 0; ih < 2; ih++) {
#pragma unroll
        for (int i = 0; i < 4; i++) {
            int r = m0 + ih * 64 + ty * 4 + i;
            if (r >= M) continue;
#pragma unroll
            for (int jh = 0; jh < 2; jh++) {
                float4 v = make_float4(acc[ih * 4 + i][jh * 4 + 0],
                                       acc[ih * 4 + i][jh * 4 + 1],
                                       acc[ih * 4 + i][jh * 4 + 2],
                                       acc[ih * 4 + i][jh * 4 + 3]);
                *(float4*)(Cp + (size_t)r * N + n0 + jh * 64 + tx * 4) = v;
            }
        }
    }
}

// ---------------- kernel 6: reduce split-K partials + bias + relu ------------
__global__ void k_reduce(const float* __restrict__ part, const float* __restrict__ bias,
                         float* __restrict__ out, int M, int N, int KS) {
    int m = blockIdx.x;
    int n = threadIdx.x;
    float s = bias[n];
    for (int z = 0; z < KS; z++) s += part[(size_t)z * M * N + (size_t)m * N + n];
    out[(size_t)m * N + n] = fmaxf(s, 0.f);
}

// ---------------- kernel 7: output heads (2 + 4 col GEMVs) -------------------
// grid NROI, block 32. Lane-strided dot products with shuffle reduction.
__global__ void k_heads(const float* __restrict__ wcls, const float* __restrict__ bcls,
                        const float* __restrict__ wreg, const float* __restrict__ breg,
                        float* __restrict__ out) {
    int row = blockIdx.x;
    int lane = threadIdx.x;
    float v[8];
#pragma unroll
    for (int i = 0; i < 8; i++) v[i] = g_h2[(size_t)row * FF + lane + 32 * i];

#pragma unroll
    for (int j = 0; j < 2; j++) {
        float s = 0.f;
#pragma unroll
        for (int i = 0; i < 8; i++) s += v[i] * wcls[(lane + 32 * i) * 2 + j];
#pragma unroll
        for (int off = 16; off > 0; off >>= 1) s += __shfl_xor_sync(0xffffffffu, s, off);
        if (lane == 0) out[row * 2 + j] = s + bcls[j];
    }
#pragma unroll
    for (int j = 0; j < 4; j++) {
        float s = 0.f;
#pragma unroll
        for (int i = 0; i < 8; i++) s += v[i] * wreg[(lane + 32 * i) * 4 + j];
#pragma unroll
        for (int off = 16; off > 0; off >>= 1) s += __shfl_xor_sync(0xffffffffu, s, off);
        if (lane == 0) out[NROI * 2 + row * 4 + j] = s + breg[j];
    }
}

// ---------------------------------------------------------------------------
extern "C" void kernel_launch(void* const* d_in, const int* in_sizes, int n_in,
                              void* d_out, int out_size) {
    const float* features = (const float*)d_in[0];
    const int* rois = (const int*)d_in[1];
    const float* w1 = (const float*)d_in[2];
    const float* b1 = (const float*)d_in[3];
    const float* w2 = (const float*)d_in[4];
    const float* b2 = (const float*)d_in[5];
    const float* w_cls = (const float*)d_in[6];
    const float* b_cls = (const float*)d_in[7];
    const float* w_reg = (const float*)d_in[8];
    const float* b_reg = (const float*)d_in[9];
    float* out = (float*)d_out;

    void* p_pooled;  cudaGetSymbolAddress(&p_pooled, g_pooled);
    void* p_w1p;     cudaGetSymbolAddress(&p_w1p, g_w1p);
    void* p_part1;   cudaGetSymbolAddress(&p_part1, g_part1);
    void* p_h1;      cudaGetSymbolAddress(&p_h1, g_h1);
    void* p_part2;   cudaGetSymbolAddress(&p_part2, g_part2);
    void* p_h2;      cudaGetSymbolAddress(&p_h2, g_h2);

    // 1) integral image (channel-innermost layout)
    k_xscan<<<dim3(HH, CCH / 32), 1024>>>(features);
    k_yscan<<<WW + 1, CCH>>>();

    // 2) ROI pooling -> [roi][p][c]
    k_pool<<<NROI, CCH>>>(rois);

    // 3) permute w1 to match pooled k-order
    k_permw1<<<K1, FF>>>(w1);

    // 4) GEMM1 (split-K=16) + reduce/bias/relu -> h1
    k_gemm<<<dim3((NROI + BM - 1) / BM, FF / BN, KS1), 256>>>(
        (const float*)p_pooled, (const float*)p_w1p, (float*)p_part1,
        NROI, FF, K1, KLEN1);
    k_reduce<<<NROI, FF>>>((const float*)p_part1, b1, (float*)p_h1, NROI, FF, KS1);

    // 5) GEMM2 (split-K=2) + reduce/bias/relu -> h2
    k_gemm<<<dim3((NROI + BM - 1) / BM, FF / BN, KS2), 256>>>(
        (const float*)p_h1, w2, (float*)p_part2, NROI, FF, FF, KLEN2);
    k_reduce<<<NROI, FF>>>((const float*)p_part2, b2, (float*)p_h2, NROI, FF, KS2);

    // 6) heads -> out[0:4000] = cls, out[4000:12000] = reg
    k_heads<<<NROI, 32>>>(w_cls, b_cls, w_reg, b_reg, out);

    (void)in_sizes; (void)n_in; (void)out_size;
}

// round 4
// speedup vs baseline: 1.2724x; 1.2724x over previous
#include <cuda_runtime.h>
#include <cuda_bf16.h>
#include <cstdint>

// Problem constants
#define CCH 256
#define HH 336
#define WW 336
#define NROI 2000
#define POOLP 7
#define K1 (CCH * POOLP * POOLP)  // 12544
#define FF 256

// ---- HMMA GEMM1 config ----
#define KSP 8                 // split-K slices
#define SLICE (K1 / KSP)      // 1568
#define NCHK (SLICE / 32)     // 49 chunks of BK=32
#define ROWB 80               // padded smem row stride in bytes (32 bf16 + 8 pad)
#define TILE_B (128 * ROWB)   // 10240 bytes per 128x32 bf16 tile
#define AH_OFF 0
#define AL_OFF (1 * TILE_B)
#define BH_OFF (2 * TILE_B)
#define BL_OFF (3 * TILE_B)
#define STAGE_B (4 * TILE_B)  // 40960
#define SMEM_TOTAL (2 * STAGE_B)

// ---- fp32 SIMT GEMM config (GEMM2) ----
#define BM 128
#define BN 128
#define BK 16
#define KS2 2
#define KLEN2 (FF / KS2)

// ---------------- static device scratch ----------------
__device__ float g_xscan[(size_t)HH * (WW + 1) * CCH];
__device__ float g_ii[(size_t)(HH + 1) * (WW + 1) * CCH];
__device__ __nv_bfloat16 g_Ahi[(size_t)NROI * K1];
__device__ __nv_bfloat16 g_Alo[(size_t)NROI * K1];
__device__ __nv_bfloat16 g_Bhi[(size_t)FF * K1];     // w1^T hi  [f][k']
__device__ __nv_bfloat16 g_Blo[(size_t)FF * K1];     // w1^T lo
__device__ float g_part1[(size_t)KSP * NROI * FF];
__device__ float g_h1[(size_t)NROI * FF];
__device__ float g_part2[(size_t)KS2 * NROI * FF];
__device__ float g_h2[(size_t)NROI * FF];

// ================= helpers =================
__device__ __forceinline__ uint32_t smem_u32(const void* p) {
    uint32_t a;
    asm("{ .reg .u64 t; cvta.to.shared.u64 t, %1; cvt.u32.u64 %0, t; }" : "=r"(a) : "l"(p));
    return a;
}
#define CPA16(sdst, gsrc) \
    asm volatile("cp.async.cg.shared.global [%0], [%1], 16;" \
                 :: "r"(sdst), "l"(__cvta_generic_to_global(gsrc)) : "memory")
#define CPA_COMMIT() asm volatile("cp.async.commit_group;" ::: "memory")
#define CPA_WAIT1()  asm volatile("cp.async.wait_group 1;" ::: "memory")

#define LDSM4(r0, r1, r2, r3, addr) \
    asm volatile("ldmatrix.sync.aligned.m8n8.x4.shared.b16 {%0,%1,%2,%3}, [%4];" \
                 : "=r"(r0), "=r"(r1), "=r"(r2), "=r"(r3) : "r"(addr))

__device__ __forceinline__ void mma16816(float* c, const uint32_t* a,
                                         uint32_t b0, uint32_t b1) {
    asm volatile(
        "mma.sync.aligned.m16n8k16.row.col.f32.bf16.bf16.f32 "
        "{%0,%1,%2,%3}, {%4,%5,%6,%7}, {%8,%9}, {%0,%1,%2,%3};"
        : "+f"(c[0]), "+f"(c[1]), "+f"(c[2]), "+f"(c[3])
        : "r"(a[0]), "r"(a[1]), "r"(a[2]), "r"(a[3]), "r"(b0), "r"(b1));
}

// ---------------- kernel 1: x-prefix scan + channel-innermost transpose ------
__global__ void k_xscan(const float* __restrict__ f) {
    __shared__ float s[32][WW + 1];
    int y = blockIdx.x, cg = blockIdx.y;
    int w = threadIdx.x >> 5, lane = threadIdx.x & 31;
    int c = cg * 32 + w;
    const float* row = f + (size_t)c * HH * WW + (size_t)y * WW;
    if (lane == 0) s[w][0] = 0.f;
    float running = 0.f;
#pragma unroll
    for (int chunk = 0; chunk < 11; chunk++) {
        int x = chunk * 32 + lane;
        float v = (x < WW) ? row[x] : 0.f;
#pragma unroll
        for (int off = 1; off < 32; off <<= 1) {
            float t = __shfl_up_sync(0xffffffffu, v, off);
            if (lane >= off) v += t;
        }
        float tot = __shfl_sync(0xffffffffu, v, 31);
        v += running;
        running += tot;
        if (x < WW) s[w][x + 1] = v;
    }
    __syncthreads();
    size_t base = (size_t)y * (WW + 1) * CCH + cg * 32;
    for (int i = threadIdx.x; i < (WW + 1) * 32; i += 1024) {
        int x = i >> 5, cl = i & 31;
        g_xscan[base + (size_t)x * CCH + cl] = s[cl][x];
    }
}

// ---------------- kernel 2: y-prefix sum ------------------------------------
__global__ void k_yscan() {
    int x = blockIdx.x, c = threadIdx.x;
    size_t off = (size_t)x * CCH + c;
    const size_t rowstride = (size_t)(WW + 1) * CCH;
    float run = 0.f;
    g_ii[off] = 0.f;
#pragma unroll 4
    for (int y = 0; y < HH; y++) {
        run += g_xscan[(size_t)y * rowstride + off];
        g_ii[(size_t)(y + 1) * rowstride + off] = run;
    }
}

// ---------------- kernel 3: ROI pool -> bf16 hi/lo split ---------------------
__global__ void k_pool(const int* __restrict__ rois) {
    int roi = blockIdx.x, c = threadIdx.x;
    int x1 = rois[roi * 4 + 0], y1 = rois[roi * 4 + 1];
    int x2 = rois[roi * 4 + 2], y2 = rois[roi * 4 + 3];
    int Ly = y2 - y1 + 1, Lx = x2 - x1 + 1;
    const size_t rowstride = (size_t)(WW + 1) * CCH;
    size_t outbase = (size_t)roi * K1 + c;
#pragma unroll
    for (int p = 0; p < POOLP * POOLP; p++) {
        int py = p / POOLP, px = p % POOLP;
        int ylo = y1 + (py * Ly) / POOLP;
        int yhi = y1 + ((py + 1) * Ly + POOLP - 1) / POOLP;
        int xlo = x1 + (px * Lx) / POOLP;
        int xhi = x1 + ((px + 1) * Lx + POOLP - 1) / POOLP;
        float s = g_ii[(size_t)yhi * rowstride + (size_t)xhi * CCH + c]
                - g_ii[(size_t)ylo * rowstride + (size_t)xhi * CCH + c]
                - g_ii[(size_t)yhi * rowstride + (size_t)xlo * CCH + c]
                + g_ii[(size_t)ylo * rowstride + (size_t)xlo * CCH + c];
        float v = s * (1.f / (float)((yhi - ylo) * (xhi - xlo)));
        __nv_bfloat16 hi = __float2bfloat16(v);
        __nv_bfloat16 lo = __float2bfloat16(v - __bfloat162float(hi));
        g_Ahi[outbase + (size_t)p * CCH] = hi;
        g_Alo[outbase + (size_t)p * CCH] = lo;
    }
}

// ---------------- kernel 4: w1 -> transposed bf16 hi/lo [f][p*256+c] ---------
// grid (49, 8, 8) = (p, c-block, f-block), block (32, 8)
__global__ void k_prep_w1(const float* __restrict__ w1) {
    __shared__ float s[32][33];
    int p = blockIdx.x, c0 = blockIdx.y * 32, f0 = blockIdx.z * 32;
    int tx = threadIdx.x, ty = threadIdx.y;
#pragma unroll
    for (int i = 0; i < 4; i++) {
        int cl = ty + i * 8;
        s[cl][tx] = w1[((size_t)(c0 + cl) * (POOLP * POOLP) + p) * FF + f0 + tx];
    }
    __syncthreads();
#pragma unroll
    for (int i = 0; i < 4; i++) {
        int fl = ty + i * 8;
        float v = s[tx][fl];
        __nv_bfloat16 hi = __float2bfloat16(v);
        __nv_bfloat16 lo = __float2bfloat16(v - __bfloat162float(hi));
        size_t idx = (size_t)(f0 + fl) * K1 + (size_t)p * CCH + c0 + tx;
        g_Bhi[idx] = hi;
        g_Blo[idx] = lo;
    }
}

// ---------------- kernel 5: HMMA bf16x3 GEMM1, split-K partials --------------
// C_part[z][m][n] = Ahi·Bhi^T + Ahi·Blo^T + Alo·Bhi^T over the z-th K slice.
// 128x128 tile, BK=32, 2-stage cp.async, 8 warps (4m x 2n), warp tile 32x64.
__global__ __launch_bounds__(256) void k_hmma1(
    const __nv_bfloat16* __restrict__ Ahi, const __nv_bfloat16* __restrict__ Alo,
    const __nv_bfloat16* __restrict__ Bhi, const __nv_bfloat16* __restrict__ Blo,
    float* __restrict__ Cpart) {
    extern __shared__ char sm[];
    const uint32_t smb = smem_u32(sm);
    const int tid = threadIdx.x;
    const int wid = tid >> 5, lane = tid & 31;
    const int m0 = blockIdx.x * 128;
    const int n0 = blockIdx.y * 128;
    const size_t kbase0 = (size_t)blockIdx.z * SLICE;

    const int warpM = (wid >> 1) * 32;  // 0,32,64,96
    const int warpN = (wid & 1) * 64;   // 0,64

    // loader mapping: thread t -> row t/2, 16B chunks 2*(t&1), 2*(t&1)+1
    const int lr = tid >> 1;
    const int lc0 = (tid & 1) * 2;
    int garow = m0 + lr;
    if (garow >= NROI) garow = NROI - 1;
    const __nv_bfloat16* gAhi = Ahi + (size_t)garow * K1;
    const __nv_bfloat16* gAlo = Alo + (size_t)garow * K1;
    const __nv_bfloat16* gBhi = Bhi + (size_t)(n0 + lr) * K1;
    const __nv_bfloat16* gBlo = Blo + (size_t)(n0 + lr) * K1;
    const uint32_t sld = smb + lr * ROWB + lc0 * 16;

    float acc[2][8][4];
#pragma unroll
    for (int mi = 0; mi < 2; mi++)
#pragma unroll
        for (int nf = 0; nf < 8; nf++)
#pragma unroll
            for (int i = 0; i < 4; i++) acc[mi][nf][i] = 0.f;

    // ---- prologue: load stage 0
    {
        size_t kk = kbase0;
#pragma unroll
        for (int i = 0; i < 2; i++) {
            uint32_t so = sld + i * 16;
            size_t go = kk + (size_t)(lc0 + i) * 8;
            CPA16(so + AH_OFF, gAhi + go);
            CPA16(so + AL_OFF, gAlo + go);
            CPA16(so + BH_OFF, gBhi + go);
            CPA16(so + BL_OFF, gBlo + go);
        }
    }
    CPA_COMMIT();

    for (int ch = 0; ch < NCHK; ch++) {
        if (ch + 1 < NCHK) {
            uint32_t st = ((ch + 1) & 1) * STAGE_B;
            size_t kk = kbase0 + (size_t)(ch + 1) * 32;
#pragma unroll
            for (int i = 0; i < 2; i++) {
                uint32_t so = sld + st + i * 16;
                size_t go = kk + (size_t)(lc0 + i) * 8;
                CPA16(so + AH_OFF, gAhi + go);
                CPA16(so + AL_OFF, gAlo + go);
                CPA16(so + BH_OFF, gBhi + go);
                CPA16(so + BL_OFF, gBlo + go);
            }
        }
        CPA_COMMIT();
        CPA_WAIT1();
        __syncthreads();

        const uint32_t sbase = smb + (ch & 1) * STAGE_B;
#pragma unroll
        for (int ks = 0; ks < 2; ks++) {
            const int k2 = ks * 32;  // byte offset of 16-element k-step
            uint32_t ah[2][4], al[2][4];
#pragma unroll
            for (int mi = 0; mi < 2; mi++) {
                uint32_t aaddr = sbase + AH_OFF +
                    (uint32_t)(warpM + mi * 16 + (lane & 15)) * ROWB + k2 +
                    ((lane >> 4) & 1) * 16;
                LDSM4(ah[mi][0], ah[mi][1], ah[mi][2], ah[mi][3], aaddr);
                LDSM4(al[mi][0], al[mi][1], al[mi][2], al[mi][3], aaddr + (AL_OFF - AH_OFF));
            }
            uint32_t bh[4][4], bl[4][4];
#pragma unroll
            for (int nb = 0; nb < 4; nb++) {
                uint32_t baddr = sbase + BH_OFF +
                    (uint32_t)(warpN + nb * 16 + (lane & 7) + ((lane >> 4) & 1) * 8) * ROWB +
                    k2 + ((lane >> 3) & 1) * 16;
                LDSM4(bh[nb][0], bh[nb][1], bh[nb][2], bh[nb][3], baddr);
                LDSM4(bl[nb][0], bl[nb][1], bl[nb][2], bl[nb][3], baddr + (BL_OFF - BH_OFF));
            }
#pragma unroll
            for (int mi = 0; mi < 2; mi++)
#pragma unroll
                for (int nf = 0; nf < 8; nf++) {
                    uint32_t b0h = bh[nf >> 1][(nf & 1) * 2];
                    uint32_t b1h = bh[nf >> 1][(nf & 1) * 2 + 1];
                    uint32_t b0l = bl[nf >> 1][(nf & 1) * 2];
                    uint32_t b1l = bl[nf >> 1][(nf & 1) * 2 + 1];
                    mma16816(acc[mi][nf], ah[mi], b0h, b1h);
                    mma16816(acc[mi][nf], ah[mi], b0l, b1l);
                    mma16816(acc[mi][nf], al[mi], b0h, b1h);
                }
        }
        __syncthreads();
    }

    // ---- epilogue: write split-K partials
    float* Cp = Cpart + (size_t)blockIdx.z * NROI * FF;
#pragma unroll
    for (int mi = 0; mi < 2; mi++) {
        int mrow = m0 + warpM + mi * 16 + (lane >> 2);
#pragma unroll
        for (int nf = 0; nf < 8; nf++) {
            int n = n0 + warpN + nf * 8 + (lane & 3) * 2;
            if (mrow < NROI) {
                float2 v = make_float2(acc[mi][nf][0], acc[mi][nf][1]);
                *(float2*)(Cp + (size_t)mrow * FF + n) = v;
            }
            if (mrow + 8 < NROI) {
                float2 v = make_float2(acc[mi][nf][2], acc[mi][nf][3]);
                *(float2*)(Cp + (size_t)(mrow + 8) * FF + n) = v;
            }
        }
    }
}

// ---------------- kernel 6: fp32 tiled GEMM (GEMM2) --------------------------
__global__ __launch_bounds__(256, 2) void k_gemm(
    const float* __restrict__ A, const float* __restrict__ B,
    float* __restrict__ Cpart, int M, int N, int K, int klen) {
    __shared__ float As[BK][BM];
    __shared__ float Bs[BK][BN];
    int m0 = blockIdx.x * BM, n0 = blockIdx.y * BN;
    int kk0 = blockIdx.z * klen;
    int tid = threadIdx.x;
    int tx = tid & 15, ty = tid >> 4;
    int lr = tid >> 2, ls = tid & 3;
    int lbk = tid >> 5, lbn = tid & 31;
    float acc[8][8];
#pragma unroll
    for (int i = 0; i < 8; i++)
#pragma unroll
        for (int j = 0; j < 8; j++) acc[i][j] = 0.f;
    float* Cp = Cpart + (size_t)blockIdx.z * M * N;
    for (int kb = 0; kb < klen; kb += BK) {
#pragma unroll
        for (int h = 0; h < 2; h++) {
            int r = lr + h * 64;
            int gm = m0 + r;
            float4 v = make_float4(0.f, 0.f, 0.f, 0.f);
            if (gm < M) v = *(const float4*)(A + (size_t)gm * K + kk0 + kb + ls * 4);
            As[ls * 4 + 0][r] = v.x;
            As[ls * 4 + 1][r] = v.y;
            As[ls * 4 + 2][r] = v.z;
            As[ls * 4 + 3][r] = v.w;
        }
#pragma unroll
        for (int h = 0; h < 2; h++) {
            int kr = lbk + h * 8;
            float4 v = *(const float4*)(B + (size_t)(kk0 + kb + kr) * N + n0 + lbn * 4);
            *(float4*)&Bs[kr][lbn * 4] = v;
        }
        __syncthreads();
#pragma unroll
        for (int kk = 0; kk < BK; kk++) {
            float a[8], b[8];
            *(float4*)&a[0] = *(const float4*)&As[kk][ty * 4];
            *(float4*)&a[4] = *(const float4*)&As[kk][64 + ty * 4];
            *(float4*)&b[0] = *(const float4*)&Bs[kk][tx * 4];
            *(float4*)&b[4] = *(const float4*)&Bs[kk][64 + tx * 4];
#pragma unroll
            for (int i = 0; i < 8; i++)
#pragma unroll
                for (int j = 0; j < 8; j++) acc[i][j] += a[i] * b[j];
        }
        __syncthreads();
    }
#pragma unroll
    for (int ih = 0; ih < 2; ih++) {
#pragma unroll
        for (int i = 0; i < 4; i++) {
            int r = m0 + ih * 64 + ty * 4 + i;
            if (r >= M) continue;
#pragma unroll
            for (int jh = 0; jh < 2; jh++) {
                float4 v = make_float4(acc[ih * 4 + i][jh * 4 + 0], acc[ih * 4 + i][jh * 4 + 1],
                                       acc[ih * 4 + i][jh * 4 + 2], acc[ih * 4 + i][jh * 4 + 3]);
                *(float4*)(Cp + (size_t)r * N + n0 + jh * 64 + tx * 4) = v;
            }
        }
    }
}

// ---------------- kernel 7: reduce split-K partials + bias + relu ------------
__global__ void k_reduce(const float* __restrict__ part, const float* __restrict__ bias,
                         float* __restrict__ out, int M, int N, int KS) {
    int m = blockIdx.x, n = threadIdx.x;
    float s = bias[n];
    for (int z = 0; z < KS; z++) s += part[(size_t)z * M * N + (size_t)m * N + n];
    out[(size_t)m * N + n] = fmaxf(s, 0.f);
}

// ---------------- kernel 8: output heads -------------------------------------
__global__ void k_heads(const float* __restrict__ wcls, const float* __restrict__ bcls,
                        const float* __restrict__ wreg, const float* __restrict__ breg,
                        float* __restrict__ out) {
    int row = blockIdx.x, lane = threadIdx.x;
    float v[8];
#pragma unroll
    for (int i = 0; i < 8; i++) v[i] = g_h2[(size_t)row * FF + lane + 32 * i];
#pragma unroll
    for (int j = 0; j < 2; j++) {
        float s = 0.f;
#pragma unroll
        for (int i = 0; i < 8; i++) s += v[i] * wcls[(lane + 32 * i) * 2 + j];
#pragma unroll
        for (int off = 16; off > 0; off >>= 1) s += __shfl_xor_sync(0xffffffffu, s, off);
        if (lane == 0) out[row * 2 + j] = s + bcls[j];
    }
#pragma unroll
    for (int j = 0; j < 4; j++) {
        float s = 0.f;
#pragma unroll
        for (int i = 0; i < 8; i++) s += v[i] * wreg[(lane + 32 * i) * 4 + j];
#pragma unroll
        for (int off = 16; off > 0; off >>= 1) s += __shfl_xor_sync(0xffffffffu, s, off);
        if (lane == 0) out[NROI * 2 + row * 4 + j] = s + breg[j];
    }
}

// ---------------------------------------------------------------------------
extern "C" void kernel_launch(void* const* d_in, const int* in_sizes, int n_in,
                              void* d_out, int out_size) {
    const float* features = (const float*)d_in[0];
    const int* rois = (const int*)d_in[1];
    const float* w1 = (const float*)d_in[2];
    const float* b1 = (const float*)d_in[3];
    const float* w2 = (const float*)d_in[4];
    const float* b2 = (const float*)d_in[5];
    const float* w_cls = (const float*)d_in[6];
    const float* b_cls = (const float*)d_in[7];
    const float* w_reg = (const float*)d_in[8];
    const float* b_reg = (const float*)d_in[9];
    float* out = (float*)d_out;

    void* p_Ahi;   cudaGetSymbolAddress(&p_Ahi, g_Ahi);
    void* p_Alo;   cudaGetSymbolAddress(&p_Alo, g_Alo);
    void* p_Bhi;   cudaGetSymbolAddress(&p_Bhi, g_Bhi);
    void* p_Blo;   cudaGetSymbolAddress(&p_Blo, g_Blo);
    void* p_part1; cudaGetSymbolAddress(&p_part1, g_part1);
    void* p_h1;    cudaGetSymbolAddress(&p_h1, g_h1);
    void* p_part2; cudaGetSymbolAddress(&p_part2, g_part2);
    void* p_h2;    cudaGetSymbolAddress(&p_h2, g_h2);

    cudaFuncSetAttribute(k_hmma1, cudaFuncAttributeMaxDynamicSharedMemorySize, SMEM_TOTAL);

    // 1) integral image (channel-innermost layout)
    k_xscan<<<dim3(HH, CCH / 32), 1024>>>(features);
    k_yscan<<<WW + 1, CCH>>>();

    // 2) ROI pooling -> bf16 hi/lo A matrix
    k_pool<<<NROI, CCH>>>(rois);

    // 3) w1 -> transposed bf16 hi/lo B matrix
    k_prep_w1<<<dim3(POOLP * POOLP, CCH / 32, FF / 32), dim3(32, 8)>>>(w1);

    // 4) GEMM1 on HMMA (bf16x3, split-K=8) + reduce/bias/relu
    k_hmma1<<<dim3((NROI + 127) / 128, 2, KSP), 256, SMEM_TOTAL>>>(
        (const __nv_bfloat16*)p_Ahi, (const __nv_bfloat16*)p_Alo,
        (const __nv_bfloat16*)p_Bhi, (const __nv_bfloat16*)p_Blo,
        (float*)p_part1);
    k_reduce<<<NROI, FF>>>((const float*)p_part1, b1, (float*)p_h1, NROI, FF, KSP);

    // 5) GEMM2 (fp32 SIMT, split-K=2) + reduce/bias/relu
    k_gemm<<<dim3((NROI + BM - 1) / BM, FF / BN, KS2), 256>>>(
        (const float*)p_h1, w2, (float*)p_part2, NROI, FF, FF, KLEN2);
    k_reduce<<<NROI, FF>>>((const float*)p_part2, b2, (float*)p_h2, NROI, FF, KS2);

    // 6) heads
    k_heads<<<NROI, 32>>>(w_cls, b_cls, w_reg, b_reg, out);

    (void)in_sizes; (void)n_in; (void)out_size;
}

// round 5
// speedup vs baseline: 1.6918x; 1.3296x over previous
#include <cuda_runtime.h>
#include <cuda_bf16.h>
#include <cstdint>

// Problem constants
#define CCH 256
#define HH 336
#define WW 336
#define NROI 2000
#define POOLP 7
#define K1 (CCH * POOLP * POOLP)  // 12544
#define FF 256

// ---- HMMA GEMM config ----
#define KSP 8                 // split-K slices for GEMM1
#define SLICE1 (K1 / KSP)     // 1568
#define NCHK1 (SLICE1 / 32)   // 49
#define ROWB 80               // padded smem row stride bytes (64B data + 16B pad)
#define AH_OFF 0
#define AL_OFF 10240          // 128*80
#define BH_OFF 20480
#define BL_OFF 40960          // BH + 256*80
#define STAGE_B 61440         // BL + 256*80
#define NSTAGE 3
#define SMEM_TOT (NSTAGE * STAGE_B)   // 184320

// ---------------- static device scratch ----------------
__device__ float g_xscan[(size_t)HH * (WW + 1) * CCH];
__device__ float g_ii[(size_t)(HH + 1) * (WW + 1) * CCH];
__device__ __nv_bfloat16 g_Ahi[(size_t)NROI * K1];
__device__ __nv_bfloat16 g_Alo[(size_t)NROI * K1];
__device__ __nv_bfloat16 g_Bhi[(size_t)FF * K1];      // w1^T hi  [f][k']
__device__ __nv_bfloat16 g_Blo[(size_t)FF * K1];      // w1^T lo
__device__ float g_part1[(size_t)KSP * NROI * FF];
__device__ __nv_bfloat16 g_h1hi[(size_t)NROI * FF];
__device__ __nv_bfloat16 g_h1lo[(size_t)NROI * FF];
__device__ __nv_bfloat16 g_B2hi[(size_t)FF * FF];     // w2^T hi  [f][k]
__device__ __nv_bfloat16 g_B2lo[(size_t)FF * FF];
__device__ float g_part2[(size_t)NROI * FF];
__device__ float g_h2[(size_t)NROI * FF];

// ================= helpers =================
__device__ __forceinline__ uint32_t smem_u32(const void* p) {
    uint32_t a;
    asm("{ .reg .u64 t; cvta.to.shared.u64 t, %1; cvt.u32.u64 %0, t; }" : "=r"(a) : "l"(p));
    return a;
}
#define CPA16(sdst, gsrc) \
    asm volatile("cp.async.cg.shared.global [%0], [%1], 16;" \
                 :: "r"(sdst), "l"(__cvta_generic_to_global(gsrc)) : "memory")
#define CPA_COMMIT() asm volatile("cp.async.commit_group;" ::: "memory")
#define CPA_WAIT2()  asm volatile("cp.async.wait_group 2;" ::: "memory")

#define LDSM4(r0, r1, r2, r3, addr) \
    asm volatile("ldmatrix.sync.aligned.m8n8.x4.shared.b16 {%0,%1,%2,%3}, [%4];" \
                 : "=r"(r0), "=r"(r1), "=r"(r2), "=r"(r3) : "r"(addr))

__device__ __forceinline__ void mma16816(float* c, const uint32_t* a,
                                         uint32_t b0, uint32_t b1) {
    asm volatile(
        "mma.sync.aligned.m16n8k16.row.col.f32.bf16.bf16.f32 "
        "{%0,%1,%2,%3}, {%4,%5,%6,%7}, {%8,%9}, {%0,%1,%2,%3};"
        : "+f"(c[0]), "+f"(c[1]), "+f"(c[2]), "+f"(c[3])
        : "r"(a[0]), "r"(a[1]), "r"(a[2]), "r"(a[3]), "r"(b0), "r"(b1));
}

// ---------------- kernel 1: x-prefix scan + channel-innermost transpose ------
__global__ void k_xscan(const float* __restrict__ f) {
    __shared__ float s[32][WW + 1];
    int y = blockIdx.x, cg = blockIdx.y;
    int w = threadIdx.x >> 5, lane = threadIdx.x & 31;
    int c = cg * 32 + w;
    const float* row = f + (size_t)c * HH * WW + (size_t)y * WW;
    if (lane == 0) s[w][0] = 0.f;
    float running = 0.f;
#pragma unroll
    for (int chunk = 0; chunk < 11; chunk++) {
        int x = chunk * 32 + lane;
        float v = (x < WW) ? row[x] : 0.f;
#pragma unroll
        for (int off = 1; off < 32; off <<= 1) {
            float t = __shfl_up_sync(0xffffffffu, v, off);
            if (lane >= off) v += t;
        }
        float tot = __shfl_sync(0xffffffffu, v, 31);
        v += running;
        running += tot;
        if (x < WW) s[w][x + 1] = v;
    }
    __syncthreads();
    size_t base = (size_t)y * (WW + 1) * CCH + cg * 32;
    for (int i = threadIdx.x; i < (WW + 1) * 32; i += 1024) {
        int x = i >> 5, cl = i & 31;
        g_xscan[base + (size_t)x * CCH + cl] = s[cl][x];
    }
}

// ---------------- kernel 2: y-prefix sum (float4, 8-deep load batches) -------
__global__ void k_yscan() {
    int idx = blockIdx.x * blockDim.x + threadIdx.x;
    if (idx >= (WW + 1) * (CCH / 4)) return;
    int x = idx / (CCH / 4), c4 = idx % (CCH / 4);
    size_t off = (size_t)x * CCH + (size_t)c4 * 4;
    const size_t rs = (size_t)(WW + 1) * CCH;
    float4 run = make_float4(0.f, 0.f, 0.f, 0.f);
    *(float4*)&g_ii[off] = run;  // y = 0 row
    for (int yb = 0; yb < HH; yb += 8) {
        float4 v[8];
#pragma unroll
        for (int i = 0; i < 8; i++)
            v[i] = *(const float4*)&g_xscan[(size_t)(yb + i) * rs + off];
#pragma unroll
        for (int i = 0; i < 8; i++) {
            run.x += v[i].x; run.y += v[i].y; run.z += v[i].z; run.w += v[i].w;
            *(float4*)&g_ii[(size_t)(yb + i + 1) * rs + off] = run;
        }
    }
}

// ---------------- kernel 3: ROI pool -> bf16 hi/lo split ---------------------
__global__ void k_pool(const int* __restrict__ rois) {
    int roi = blockIdx.x, c = threadIdx.x;
    int x1 = rois[roi * 4 + 0], y1 = rois[roi * 4 + 1];
    int x2 = rois[roi * 4 + 2], y2 = rois[roi * 4 + 3];
    int Ly = y2 - y1 + 1, Lx = x2 - x1 + 1;
    const size_t rowstride = (size_t)(WW + 1) * CCH;
    size_t outbase = (size_t)roi * K1 + c;
#pragma unroll
    for (int p = 0; p < POOLP * POOLP; p++) {
        int py = p / POOLP, px = p % POOLP;
        int ylo = y1 + (py * Ly) / POOLP;
        int yhi = y1 + ((py + 1) * Ly + POOLP - 1) / POOLP;
        int xlo = x1 + (px * Lx) / POOLP;
        int xhi = x1 + ((px + 1) * Lx + POOLP - 1) / POOLP;
        float s = g_ii[(size_t)yhi * rowstride + (size_t)xhi * CCH + c]
                - g_ii[(size_t)ylo * rowstride + (size_t)xhi * CCH + c]
                - g_ii[(size_t)yhi * rowstride + (size_t)xlo * CCH + c]
                + g_ii[(size_t)ylo * rowstride + (size_t)xlo * CCH + c];
        float v = s * (1.f / (float)((yhi - ylo) * (xhi - xlo)));
        __nv_bfloat16 hi = __float2bfloat16(v);
        __nv_bfloat16 lo = __float2bfloat16(v - __bfloat162float(hi));
        g_Ahi[outbase + (size_t)p * CCH] = hi;
        g_Alo[outbase + (size_t)p * CCH] = lo;
    }
}

// ---------------- kernel 4: w1 -> transposed bf16 hi/lo [f][p*256+c] ---------
__global__ void k_prep_w1(const float* __restrict__ w1) {
    __shared__ float s[32][33];
    int p = blockIdx.x, c0 = blockIdx.y * 32, f0 = blockIdx.z * 32;
    int tx = threadIdx.x, ty = threadIdx.y;
#pragma unroll
    for (int i = 0; i < 4; i++) {
        int cl = ty + i * 8;
        s[cl][tx] = w1[((size_t)(c0 + cl) * (POOLP * POOLP) + p) * FF + f0 + tx];
    }
    __syncthreads();
#pragma unroll
    for (int i = 0; i < 4; i++) {
        int fl = ty + i * 8;
        float v = s[tx][fl];
        __nv_bfloat16 hi = __float2bfloat16(v);
        __nv_bfloat16 lo = __float2bfloat16(v - __bfloat162float(hi));
        size_t idx = (size_t)(f0 + fl) * K1 + (size_t)p * CCH + c0 + tx;
        g_Bhi[idx] = hi;
        g_Blo[idx] = lo;
    }
}

// ---------------- kernel 4b: w2 -> transposed bf16 hi/lo [f][k] --------------
__global__ void k_prep_w2(const float* __restrict__ w2) {
    __shared__ float s[32][33];
    int k0 = blockIdx.x * 32, f0 = blockIdx.y * 32;
    int tx = threadIdx.x, ty = threadIdx.y;
#pragma unroll
    for (int i = 0; i < 4; i++) {
        int kl = ty + i * 8;
        s[kl][tx] = w2[(size_t)(k0 + kl) * FF + f0 + tx];
    }
    __syncthreads();
#pragma unroll
    for (int i = 0; i < 4; i++) {
        int fl = ty + i * 8;
        float v = s[tx][fl];
        __nv_bfloat16 hi = __float2bfloat16(v);
        __nv_bfloat16 lo = __float2bfloat16(v - __bfloat162float(hi));
        size_t idx = (size_t)(f0 + fl) * FF + k0 + tx;
        g_B2hi[idx] = hi;
        g_B2lo[idx] = lo;
    }
}

// ---------------- kernel 5: HMMA bf16x3 GEMM (generic M/K/slice) -------------
// C_part[z][m][0:256] += Ahi·Bhi^T + Ahi·Blo^T + Alo·Bhi^T over slice z.
// 128x256 tile, BK=32, 3-stage cp.async, 16 warps (4m x 4n), warp tile 32x64.
__global__ __launch_bounds__(512) void k_hmma(
    const __nv_bfloat16* __restrict__ Ahi, const __nv_bfloat16* __restrict__ Alo,
    const __nv_bfloat16* __restrict__ Bhi, const __nv_bfloat16* __restrict__ Blo,
    float* __restrict__ Cpart, int M, int Kd, int slice, int nchk) {
    extern __shared__ char sm[];
    const uint32_t smb = smem_u32(sm);
    const int tid = threadIdx.x;
    const int wid = tid >> 5, lane = tid & 31;
    const int m0 = blockIdx.x * 128;
    const size_t kbase = (size_t)blockIdx.z * slice;

    const int warpM = (wid >> 2) * 32;   // 0,32,64,96
    const int warpN = (wid & 3) * 64;    // 0,64,128,192

    // loader mapping: thread t -> row t>>2, 16B chunk t&3
    const int lr = tid >> 2;
    const int lch = tid & 3;
    int garow = m0 + lr;
    if (garow >= M) garow = M - 1;
    const __nv_bfloat16* gAhi = Ahi + (size_t)garow * Kd + lch * 8;
    const __nv_bfloat16* gAlo = Alo + (size_t)garow * Kd + lch * 8;
    const __nv_bfloat16* gB0hi = Bhi + (size_t)lr * Kd + lch * 8;
    const __nv_bfloat16* gB0lo = Blo + (size_t)lr * Kd + lch * 8;
    const __nv_bfloat16* gB1hi = Bhi + (size_t)(lr + 128) * Kd + lch * 8;
    const __nv_bfloat16* gB1lo = Blo + (size_t)(lr + 128) * Kd + lch * 8;
    const uint32_t aoff = (uint32_t)lr * ROWB + lch * 16;
    const uint32_t boff0 = aoff;
    const uint32_t boff1 = (uint32_t)(lr + 128) * ROWB + lch * 16;

    float acc[2][8][4];
#pragma unroll
    for (int mi = 0; mi < 2; mi++)
#pragma unroll
        for (int nf = 0; nf < 8; nf++)
#pragma unroll
            for (int i = 0; i < 4; i++) acc[mi][nf][i] = 0.f;

#define LOAD_STAGE(stg, chv) do {                                   \
        uint32_t sb_ = smb + (uint32_t)(stg) * STAGE_B;             \
        size_t kk_ = kbase + (size_t)(chv) * 32;                    \
        CPA16(sb_ + AH_OFF + aoff, gAhi + kk_);                     \
        CPA16(sb_ + AL_OFF + aoff, gAlo + kk_);                     \
        CPA16(sb_ + BH_OFF + boff0, gB0hi + kk_);                   \
        CPA16(sb_ + BL_OFF + boff0, gB0lo + kk_);                   \
        CPA16(sb_ + BH_OFF + boff1, gB1hi + kk_);                   \
        CPA16(sb_ + BL_OFF + boff1, gB1lo + kk_);                   \
    } while (0)

    LOAD_STAGE(0, 0);
    CPA_COMMIT();
    if (nchk > 1) LOAD_STAGE(1, 1);
    CPA_COMMIT();

    int stg = 0;
    for (int ch = 0; ch < nchk; ch++) {
        if (ch + 2 < nchk) {
            int s2 = stg + 2; if (s2 >= NSTAGE) s2 -= NSTAGE;
            LOAD_STAGE(s2, ch + 2);
        }
        CPA_COMMIT();
        CPA_WAIT2();
        __syncthreads();

        const uint32_t sbase = smb + (uint32_t)stg * STAGE_B;
#pragma unroll
        for (int ks = 0; ks < 2; ks++) {
            const int k2 = ks * 32;
            uint32_t ah[2][4], al[2][4];
#pragma unroll
            for (int mi = 0; mi < 2; mi++) {
                uint32_t aaddr = sbase + AH_OFF +
                    (uint32_t)(warpM + mi * 16 + (lane & 15)) * ROWB + k2 +
                    ((lane >> 4) & 1) * 16;
                LDSM4(ah[mi][0], ah[mi][1], ah[mi][2], ah[mi][3], aaddr);
                LDSM4(al[mi][0], al[mi][1], al[mi][2], al[mi][3], aaddr + (AL_OFF - AH_OFF));
            }
#pragma unroll
            for (int half = 0; half < 2; half++) {
                uint32_t bh[2][4], bl[2][4];
#pragma unroll
                for (int j = 0; j < 2; j++) {
                    int nb = half * 2 + j;
                    uint32_t baddr = sbase + BH_OFF +
                        (uint32_t)(warpN + nb * 16 + (lane & 7) + ((lane >> 4) & 1) * 8) * ROWB +
                        k2 + ((lane >> 3) & 1) * 16;
                    LDSM4(bh[j][0], bh[j][1], bh[j][2], bh[j][3], baddr);
                    LDSM4(bl[j][0], bl[j][1], bl[j][2], bl[j][3], baddr + (BL_OFF - BH_OFF));
                }
#pragma unroll
                for (int mi = 0; mi < 2; mi++)
#pragma unroll
                    for (int jf = 0; jf < 4; jf++) {
                        int j = jf >> 1;
                        uint32_t b0h = bh[j][(jf & 1) * 2], b1h = bh[j][(jf & 1) * 2 + 1];
                        uint32_t b0l = bl[j][(jf & 1) * 2], b1l = bl[j][(jf & 1) * 2 + 1];
                        float* a4 = acc[mi][half * 4 + jf];
                        mma16816(a4, ah[mi], b0h, b1h);
                        mma16816(a4, ah[mi], b0l, b1l);
                        mma16816(a4, al[mi], b0h, b1h);
                    }
            }
        }
        __syncthreads();
        stg++; if (stg >= NSTAGE) stg = 0;
    }
#undef LOAD_STAGE

    float* Cp = Cpart + (size_t)blockIdx.z * M * FF;
#pragma unroll
    for (int mi = 0; mi < 2; mi++) {
        int mrow = m0 + warpM + mi * 16 + (lane >> 2);
#pragma unroll
        for (int nf = 0; nf < 8; nf++) {
            int n = warpN + nf * 8 + (lane & 3) * 2;
            if (mrow < M)
                *(float2*)(Cp + (size_t)mrow * FF + n) =
                    make_float2(acc[mi][nf][0], acc[mi][nf][1]);
            if (mrow + 8 < M)
                *(float2*)(Cp + (size_t)(mrow + 8) * FF + n) =
                    make_float2(acc[mi][nf][2], acc[mi][nf][3]);
        }
    }
}

// ---------------- kernel 6: reduce partials + bias + relu -> bf16 hi/lo ------
__global__ void k_reduce_bf(const float* __restrict__ part, const float* __restrict__ bias) {
    int m = blockIdx.x, n = threadIdx.x;
    float s = bias[n];
#pragma unroll
    for (int z = 0; z < KSP; z++) s += part[(size_t)z * NROI * FF + (size_t)m * FF + n];
    float h = fmaxf(s, 0.f);
    __nv_bfloat16 hi = __float2bfloat16(h);
    __nv_bfloat16 lo = __float2bfloat16(h - __bfloat162float(hi));
    g_h1hi[(size_t)m * FF + n] = hi;
    g_h1lo[(size_t)m * FF + n] = lo;
}

// ---------------- kernel 7: bias + relu (GEMM2, no split-K) ------------------
__global__ void k_bias2(const float* __restrict__ part, const float* __restrict__ bias) {
    int m = blockIdx.x, n = threadIdx.x;
    g_h2[(size_t)m * FF + n] = fmaxf(part[(size_t)m * FF + n] + bias[n], 0.f);
}

// ---------------- kernel 8: output heads -------------------------------------
__global__ void k_heads(const float* __restrict__ wcls, const float* __restrict__ bcls,
                        const float* __restrict__ wreg, const float* __restrict__ breg,
                        float* __restrict__ out) {
    int row = blockIdx.x, lane = threadIdx.x;
    float v[8];
#pragma unroll
    for (int i = 0; i < 8; i++) v[i] = g_h2[(size_t)row * FF + lane + 32 * i];
#pragma unroll
    for (int j = 0; j < 2; j++) {
        float s = 0.f;
#pragma unroll
        for (int i = 0; i < 8; i++) s += v[i] * wcls[(lane + 32 * i) * 2 + j];
#pragma unroll
        for (int off = 16; off > 0; off >>= 1) s += __shfl_xor_sync(0xffffffffu, s, off);
        if (lane == 0) out[row * 2 + j] = s + bcls[j];
    }
#pragma unroll
    for (int j = 0; j < 4; j++) {
        float s = 0.f;
#pragma unroll
        for (int i = 0; i < 8; i++) s += v[i] * wreg[(lane + 32 * i) * 4 + j];
#pragma unroll
        for (int off = 16; off > 0; off >>= 1) s += __shfl_xor_sync(0xffffffffu, s, off);
        if (lane == 0) out[NROI * 2 + row * 4 + j] = s + breg[j];
    }
}

// ---------------------------------------------------------------------------
extern "C" void kernel_launch(void* const* d_in, const int* in_sizes, int n_in,
                              void* d_out, int out_size) {
    const float* features = (const float*)d_in[0];
    const int* rois = (const int*)d_in[1];
    const float* w1 = (const float*)d_in[2];
    const float* b1 = (const float*)d_in[3];
    const float* w2 = (const float*)d_in[4];
    const float* b2 = (const float*)d_in[5];
    const float* w_cls = (const float*)d_in[6];
    const float* b_cls = (const float*)d_in[7];
    const float* w_reg = (const float*)d_in[8];
    const float* b_reg = (const float*)d_in[9];
    float* out = (float*)d_out;

    void* p_Ahi;   cudaGetSymbolAddress(&p_Ahi, g_Ahi);
    void* p_Alo;   cudaGetSymbolAddress(&p_Alo, g_Alo);
    void* p_Bhi;   cudaGetSymbolAddress(&p_Bhi, g_Bhi);
    void* p_Blo;   cudaGetSymbolAddress(&p_Blo, g_Blo);
    void* p_part1; cudaGetSymbolAddress(&p_part1, g_part1);
    void* p_h1hi;  cudaGetSymbolAddress(&p_h1hi, g_h1hi);
    void* p_h1lo;  cudaGetSymbolAddress(&p_h1lo, g_h1lo);
    void* p_B2hi;  cudaGetSymbolAddress(&p_B2hi, g_B2hi);
    void* p_B2lo;  cudaGetSymbolAddress(&p_B2lo, g_B2lo);
    void* p_part2; cudaGetSymbolAddress(&p_part2, g_part2);

    cudaFuncSetAttribute(k_hmma, cudaFuncAttributeMaxDynamicSharedMemorySize, SMEM_TOT);

    // 1) integral image (channel-innermost layout)
    k_xscan<<<dim3(HH, CCH / 32), 1024>>>(features);
    k_yscan<<<((WW + 1) * (CCH / 4) + 255) / 256, 256>>>();

    // 2) ROI pooling -> bf16 hi/lo A matrix
    k_pool<<<NROI, CCH>>>(rois);

    // 3) weight prep
    k_prep_w1<<<dim3(POOLP * POOLP, CCH / 32, FF / 32), dim3(32, 8)>>>(w1);
    k_prep_w2<<<dim3(FF / 32, FF / 32), dim3(32, 8)>>>(w2);

    // 4) GEMM1 on HMMA (bf16x3, BN=256, split-K=8) + reduce/bias/relu -> h1 hi/lo
    k_hmma<<<dim3((NROI + 127) / 128, 1, KSP), 512, SMEM_TOT>>>(
        (const __nv_bfloat16*)p_Ahi, (const __nv_bfloat16*)p_Alo,
        (const __nv_bfloat16*)p_Bhi, (const __nv_bfloat16*)p_Blo,
        (float*)p_part1, NROI, K1, SLICE1, NCHK1);
    k_reduce_bf<<<NROI, FF>>>((const float*)p_part1, b1);

    // 5) GEMM2 on HMMA (bf16x3, K=256, no split-K) + bias/relu -> h2
    k_hmma<<<dim3((NROI + 127) / 128, 1, 1), 512, SMEM_TOT>>>(
        (const __nv_bfloat16*)p_h1hi, (const __nv_bfloat16*)p_h1lo,
        (const __nv_bfloat16*)p_B2hi, (const __nv_bfloat16*)p_B2lo,
        (float*)p_part2, NROI, FF, FF, FF / 32);
    k_bias2<<<NROI, FF>>>((const float*)p_part2, b2);

    // 6) heads
    k_heads<<<NROI, 32>>>(w_cls, b_cls, w_reg, b_reg, out);

    (void)in_sizes; (void)n_in; (void)out_size;
}

// round 6
// speedup vs baseline: 2.0333x; 1.2019x over previous
#include <cuda_runtime.h>
#include <cuda_fp16.h>
#include <cstdint>

// Problem constants
#define CCH 256
#define HH 336
#define WW 336
#define NROI 2000
#define POOLP 7
#define K1 (CCH * POOLP * POOLP)  // 12544
#define FF 256

// ---- HMMA GEMM config ----
#define KSP 8                 // split-K slices for GEMM1
#define SLICE1 (K1 / KSP)     // 1568
#define NCHK1 (SLICE1 / 32)   // 49
#define ROWB 80               // padded smem row stride bytes (64B data + 16B pad)
#define NSTAGE 3

// ---------------- static device scratch ----------------
__device__ float g_xscan[(size_t)HH * (WW + 1) * CCH];
__device__ float g_ii[(size_t)(HH + 1) * (WW + 1) * CCH];
__device__ __half g_Ahf[(size_t)NROI * K1];          // pooled A, fp16 (single)
__device__ __half g_Bhi[(size_t)FF * K1];            // w1^T hi  [f][k']
__device__ __half g_Blo[(size_t)FF * K1];            // w1^T lo
__device__ float g_part1[(size_t)KSP * NROI * FF];
__device__ __half g_h1hi[(size_t)NROI * FF];
__device__ __half g_h1lo[(size_t)NROI * FF];
__device__ __half g_B2hi[(size_t)FF * FF];           // w2^T hi  [f][k]
__device__ __half g_B2lo[(size_t)FF * FF];
__device__ float g_part2[(size_t)NROI * FF];
__device__ float g_h2[(size_t)NROI * FF];

// ================= helpers =================
__device__ __forceinline__ uint32_t smem_u32(const void* p) {
    uint32_t a;
    asm("{ .reg .u64 t; cvta.to.shared.u64 t, %1; cvt.u32.u64 %0, t; }" : "=r"(a) : "l"(p));
    return a;
}
#define CPA16(sdst, gsrc) \
    asm volatile("cp.async.cg.shared.global [%0], [%1], 16;" \
                 :: "r"(sdst), "l"(__cvta_generic_to_global(gsrc)) : "memory")
#define CPA_COMMIT() asm volatile("cp.async.commit_group;" ::: "memory")
#define CPA_WAIT2()  asm volatile("cp.async.wait_group 2;" ::: "memory")

#define LDSM4(r0, r1, r2, r3, addr) \
    asm volatile("ldmatrix.sync.aligned.m8n8.x4.shared.b16 {%0,%1,%2,%3}, [%4];" \
                 : "=r"(r0), "=r"(r1), "=r"(r2), "=r"(r3) : "r"(addr))

__device__ __forceinline__ void mma16816(float* c, const uint32_t* a,
                                         uint32_t b0, uint32_t b1) {
    asm volatile(
        "mma.sync.aligned.m16n8k16.row.col.f32.f16.f16.f32 "
        "{%0,%1,%2,%3}, {%4,%5,%6,%7}, {%8,%9}, {%0,%1,%2,%3};"
        : "+f"(c[0]), "+f"(c[1]), "+f"(c[2]), "+f"(c[3])
        : "r"(a[0]), "r"(a[1]), "r"(a[2]), "r"(a[3]), "r"(b0), "r"(b1));
}

// ---------------- kernel 1: x-prefix scan + channel-innermost transpose ------
__global__ void k_xscan(const float* __restrict__ f) {
    __shared__ float s[32][WW + 1];
    int y = blockIdx.x, cg = blockIdx.y;
    int w = threadIdx.x >> 5, lane = threadIdx.x & 31;
    int c = cg * 32 + w;
    const float* row = f + (size_t)c * HH * WW + (size_t)y * WW;
    if (lane == 0) s[w][0] = 0.f;
    float running = 0.f;
#pragma unroll
    for (int chunk = 0; chunk < 11; chunk++) {
        int x = chunk * 32 + lane;
        float v = (x < WW) ? row[x] : 0.f;
#pragma unroll
        for (int off = 1; off < 32; off <<= 1) {
            float t = __shfl_up_sync(0xffffffffu, v, off);
            if (lane >= off) v += t;
        }
        float tot = __shfl_sync(0xffffffffu, v, 31);
        v += running;
        running += tot;
        if (x < WW) s[w][x + 1] = v;
    }
    __syncthreads();
    size_t base = (size_t)y * (WW + 1) * CCH + cg * 32;
    for (int i = threadIdx.x; i < (WW + 1) * 32; i += 1024) {
        int x = i >> 5, cl = i & 31;
        g_xscan[base + (size_t)x * CCH + cl] = s[cl][x];
    }
}

// ---------------- kernel 2: y-prefix sum (float4, 8-deep load batches) -------
__global__ void k_yscan() {
    int idx = blockIdx.x * blockDim.x + threadIdx.x;
    if (idx >= (WW + 1) * (CCH / 4)) return;
    int x = idx / (CCH / 4), c4 = idx % (CCH / 4);
    size_t off = (size_t)x * CCH + (size_t)c4 * 4;
    const size_t rs = (size_t)(WW + 1) * CCH;
    float4 run = make_float4(0.f, 0.f, 0.f, 0.f);
    *(float4*)&g_ii[off] = run;  // y = 0 row
    for (int yb = 0; yb < HH; yb += 8) {
        float4 v[8];
#pragma unroll
        for (int i = 0; i < 8; i++)
            v[i] = *(const float4*)&g_xscan[(size_t)(yb + i) * rs + off];
#pragma unroll
        for (int i = 0; i < 8; i++) {
            run.x += v[i].x; run.y += v[i].y; run.z += v[i].z; run.w += v[i].w;
            *(float4*)&g_ii[(size_t)(yb + i + 1) * rs + off] = run;
        }
    }
}

// ---------------- kernel 3: ROI pool -> fp16 A ------------------------------
__global__ void k_pool(const int* __restrict__ rois) {
    int roi = blockIdx.x, c = threadIdx.x;
    int x1 = rois[roi * 4 + 0], y1 = rois[roi * 4 + 1];
    int x2 = rois[roi * 4 + 2], y2 = rois[roi * 4 + 3];
    int Ly = y2 - y1 + 1, Lx = x2 - x1 + 1;
    const size_t rowstride = (size_t)(WW + 1) * CCH;
    size_t outbase = (size_t)roi * K1 + c;
#pragma unroll
    for (int p = 0; p < POOLP * POOLP; p++) {
        int py = p / POOLP, px = p % POOLP;
        int ylo = y1 + (py * Ly) / POOLP;
        int yhi = y1 + ((py + 1) * Ly + POOLP - 1) / POOLP;
        int xlo = x1 + (px * Lx) / POOLP;
        int xhi = x1 + ((px + 1) * Lx + POOLP - 1) / POOLP;
        float s = g_ii[(size_t)yhi * rowstride + (size_t)xhi * CCH + c]
                - g_ii[(size_t)ylo * rowstride + (size_t)xhi * CCH + c]
                - g_ii[(size_t)yhi * rowstride + (size_t)xlo * CCH + c]
                + g_ii[(size_t)ylo * rowstride + (size_t)xlo * CCH + c];
        float v = s * (1.f / (float)((yhi - ylo) * (xhi - xlo)));
        g_Ahf[outbase + (size_t)p * CCH] = __float2half_rn(v);
    }
}

// ---------------- kernel 4: w1 -> transposed fp16 hi/lo [f][p*256+c] ---------
__global__ void k_prep_w1(const float* __restrict__ w1) {
    __shared__ float s[32][33];
    int p = blockIdx.x, c0 = blockIdx.y * 32, f0 = blockIdx.z * 32;
    int tx = threadIdx.x, ty = threadIdx.y;
#pragma unroll
    for (int i = 0; i < 4; i++) {
        int cl = ty + i * 8;
        s[cl][tx] = w1[((size_t)(c0 + cl) * (POOLP * POOLP) + p) * FF + f0 + tx];
    }
    __syncthreads();
#pragma unroll
    for (int i = 0; i < 4; i++) {
        int fl = ty + i * 8;
        float v = s[tx][fl];
        __half hi = __float2half_rn(v);
        __half lo = __float2half_rn(v - __half2float(hi));
        size_t idx = (size_t)(f0 + fl) * K1 + (size_t)p * CCH + c0 + tx;
        g_Bhi[idx] = hi;
        g_Blo[idx] = lo;
    }
}

// ---------------- kernel 4b: w2 -> transposed fp16 hi/lo [f][k] --------------
__global__ void k_prep_w2(const float* __restrict__ w2) {
    __shared__ float s[32][33];
    int k0 = blockIdx.x * 32, f0 = blockIdx.y * 32;
    int tx = threadIdx.x, ty = threadIdx.y;
#pragma unroll
    for (int i = 0; i < 4; i++) {
        int kl = ty + i * 8;
        s[kl][tx] = w2[(size_t)(k0 + kl) * FF + f0 + tx];
    }
    __syncthreads();
#pragma unroll
    for (int i = 0; i < 4; i++) {
        int fl = ty + i * 8;
        float v = s[tx][fl];
        __half hi = __float2half_rn(v);
        __half lo = __float2half_rn(v - __half2float(hi));
        size_t idx = (size_t)(f0 + fl) * FF + k0 + tx;
        g_B2hi[idx] = hi;
        g_B2lo[idx] = lo;
    }
}

// ---------------- kernel 5: HMMA fp16 GEMM (generic M/K/slice) ---------------
// HAS_ALO = false: C = A·Bhi^T + A·Blo^T          (GEMM1, 2-term)
// HAS_ALO = true:  C = Ahi·Bhi^T + Ahi·Blo^T + Alo·Bhi^T  (GEMM2, 3-term)
// 128x256 tile, BK=32, 3-stage cp.async, 16 warps (4m x 4n), warp tile 32x64.
template <bool HAS_ALO>
__global__ __launch_bounds__(512) void k_hmma(
    const __half* __restrict__ Ahi, const __half* __restrict__ Alo,
    const __half* __restrict__ Bhi, const __half* __restrict__ Blo,
    float* __restrict__ Cpart, int M, int Kd, int slice, int nchk) {
    constexpr uint32_t AH_OFF = 0;
    constexpr uint32_t AL_OFF = 10240;
    constexpr uint32_t BH_OFF = HAS_ALO ? 20480u : 10240u;
    constexpr uint32_t BL_OFF = BH_OFF + 20480u;
    constexpr uint32_t STAGE_B = BL_OFF + 20480u;  // 51200 or 61440

    extern __shared__ char sm[];
    const uint32_t smb = smem_u32(sm);
    const int tid = threadIdx.x;
    const int wid = tid >> 5, lane = tid & 31;
    const int m0 = blockIdx.x * 128;
    const size_t kbase = (size_t)blockIdx.z * slice;

    const int warpM = (wid >> 2) * 32;   // 0,32,64,96
    const int warpN = (wid & 3) * 64;    // 0,64,128,192

    // loader mapping: thread t -> row t>>2, 16B chunk t&3
    const int lr = tid >> 2;
    const int lch = tid & 3;
    int garow = m0 + lr;
    if (garow >= M) garow = M - 1;
    const __half* gAhi = Ahi + (size_t)garow * Kd + lch * 8;
    const __half* gAlo = Alo + (size_t)garow * Kd + lch * 8;
    const __half* gB0hi = Bhi + (size_t)lr * Kd + lch * 8;
    const __half* gB0lo = Blo + (size_t)lr * Kd + lch * 8;
    const __half* gB1hi = Bhi + (size_t)(lr + 128) * Kd + lch * 8;
    const __half* gB1lo = Blo + (size_t)(lr + 128) * Kd + lch * 8;
    const uint32_t aoff = (uint32_t)lr * ROWB + lch * 16;
    const uint32_t boff0 = aoff;
    const uint32_t boff1 = (uint32_t)(lr + 128) * ROWB + lch * 16;

    float acc[2][8][4];
#pragma unroll
    for (int mi = 0; mi < 2; mi++)
#pragma unroll
        for (int nf = 0; nf < 8; nf++)
#pragma unroll
            for (int i = 0; i < 4; i++) acc[mi][nf][i] = 0.f;

#define LOAD_STAGE(stg, chv) do {                                   \
        uint32_t sb_ = smb + (uint32_t)(stg) * STAGE_B;             \
        size_t kk_ = kbase + (size_t)(chv) * 32;                    \
        CPA16(sb_ + AH_OFF + aoff, gAhi + kk_);                     \
        if (HAS_ALO) CPA16(sb_ + AL_OFF + aoff, gAlo + kk_);        \
        CPA16(sb_ + BH_OFF + boff0, gB0hi + kk_);                   \
        CPA16(sb_ + BL_OFF + boff0, gB0lo + kk_);                   \
        CPA16(sb_ + BH_OFF + boff1, gB1hi + kk_);                   \
        CPA16(sb_ + BL_OFF + boff1, gB1lo + kk_);                   \
    } while (0)

    LOAD_STAGE(0, 0);
    CPA_COMMIT();
    if (nchk > 1) LOAD_STAGE(1, 1);
    CPA_COMMIT();

    int stg = 0;
    for (int ch = 0; ch < nchk; ch++) {
        if (ch + 2 < nchk) {
            int s2 = stg + 2; if (s2 >= NSTAGE) s2 -= NSTAGE;
            LOAD_STAGE(s2, ch + 2);
        }
        CPA_COMMIT();
        CPA_WAIT2();
        __syncthreads();

        const uint32_t sbase = smb + (uint32_t)stg * STAGE_B;
#pragma unroll
        for (int ks = 0; ks < 2; ks++) {
            const int k2 = ks * 32;
            uint32_t ah[2][4], al[2][4];
#pragma unroll
            for (int mi = 0; mi < 2; mi++) {
                uint32_t aaddr = sbase + AH_OFF +
                    (uint32_t)(warpM + mi * 16 + (lane & 15)) * ROWB + k2 +
                    ((lane >> 4) & 1) * 16;
                LDSM4(ah[mi][0], ah[mi][1], ah[mi][2], ah[mi][3], aaddr);
                if (HAS_ALO)
                    LDSM4(al[mi][0], al[mi][1], al[mi][2], al[mi][3],
                          aaddr + (AL_OFF - AH_OFF));
            }
#pragma unroll
            for (int half = 0; half < 2; half++) {
                uint32_t bh[2][4], bl[2][4];
#pragma unroll
                for (int j = 0; j < 2; j++) {
                    int nb = half * 2 + j;
                    uint32_t baddr = sbase + BH_OFF +
                        (uint32_t)(warpN + nb * 16 + (lane & 7) + ((lane >> 4) & 1) * 8) * ROWB +
                        k2 + ((lane >> 3) & 1) * 16;
                    LDSM4(bh[j][0], bh[j][1], bh[j][2], bh[j][3], baddr);
                    LDSM4(bl[j][0], bl[j][1], bl[j][2], bl[j][3], baddr + (BL_OFF - BH_OFF));
                }
#pragma unroll
                for (int mi = 0; mi < 2; mi++)
#pragma unroll
                    for (int jf = 0; jf < 4; jf++) {
                        int j = jf >> 1;
                        uint32_t b0h = bh[j][(jf & 1) * 2], b1h = bh[j][(jf & 1) * 2 + 1];
                        uint32_t b0l = bl[j][(jf & 1) * 2], b1l = bl[j][(jf & 1) * 2 + 1];
                        float* a4 = acc[mi][half * 4 + jf];
                        mma16816(a4, ah[mi], b0h, b1h);
                        mma16816(a4, ah[mi], b0l, b1l);
                        if (HAS_ALO) mma16816(a4, al[mi], b0h, b1h);
                    }
            }
        }
        __syncthreads();
        stg++; if (stg >= NSTAGE) stg = 0;
    }
#undef LOAD_STAGE

    float* Cp = Cpart + (size_t)blockIdx.z * M * FF;
#pragma unroll
    for (int mi = 0; mi < 2; mi++) {
        int mrow = m0 + warpM + mi * 16 + (lane >> 2);
#pragma unroll
        for (int nf = 0; nf < 8; nf++) {
            int n = warpN + nf * 8 + (lane & 3) * 2;
            if (mrow < M)
                *(float2*)(Cp + (size_t)mrow * FF + n) =
                    make_float2(acc[mi][nf][0], acc[mi][nf][1]);
            if (mrow + 8 < M)
                *(float2*)(Cp + (size_t)(mrow + 8) * FF + n) =
                    make_float2(acc[mi][nf][2], acc[mi][nf][3]);
        }
    }
}

// ---------------- kernel 6: reduce partials + bias + relu -> fp16 hi/lo ------
__global__ void k_reduce_hf(const float* __restrict__ part, const float* __restrict__ bias) {
    int m = blockIdx.x, n = threadIdx.x;
    float s = bias[n];
#pragma unroll
    for (int z = 0; z < KSP; z++) s += part[(size_t)z * NROI * FF + (size_t)m * FF + n];
    float h = fmaxf(s, 0.f);
    __half hi = __float2half_rn(h);
    __half lo = __float2half_rn(h - __half2float(hi));
    g_h1hi[(size_t)m * FF + n] = hi;
    g_h1lo[(size_t)m * FF + n] = lo;
}

// ---------------- kernel 7: bias + relu (GEMM2, no split-K) ------------------
__global__ void k_bias2(const float* __restrict__ part, const float* __restrict__ bias) {
    int m = blockIdx.x, n = threadIdx.x;
    g_h2[(size_t)m * FF + n] = fmaxf(part[(size_t)m * FF + n] + bias[n], 0.f);
}

// ---------------- kernel 8: output heads -------------------------------------
__global__ void k_heads(const float* __restrict__ wcls, const float* __restrict__ bcls,
                        const float* __restrict__ wreg, const float* __restrict__ breg,
                        float* __restrict__ out) {
    int row = blockIdx.x, lane = threadIdx.x;
    float v[8];
#pragma unroll
    for (int i = 0; i < 8; i++) v[i] = g_h2[(size_t)row * FF + lane + 32 * i];
#pragma unroll
    for (int j = 0; j < 2; j++) {
        float s = 0.f;
#pragma unroll
        for (int i = 0; i < 8; i++) s += v[i] * wcls[(lane + 32 * i) * 2 + j];
#pragma unroll
        for (int off = 16; off > 0; off >>= 1) s += __shfl_xor_sync(0xffffffffu, s, off);
        if (lane == 0) out[row * 2 + j] = s + bcls[j];
    }
#pragma unroll
    for (int j = 0; j < 4; j++) {
        float s = 0.f;
#pragma unroll
        for (int i = 0; i < 8; i++) s += v[i] * wreg[(lane + 32 * i) * 4 + j];
#pragma unroll
        for (int off = 16; off > 0; off >>= 1) s += __shfl_xor_sync(0xffffffffu, s, off);
        if (lane == 0) out[NROI * 2 + row * 4 + j] = s + breg[j];
    }
}

// ---------------------------------------------------------------------------
extern "C" void kernel_launch(void* const* d_in, const int* in_sizes, int n_in,
                              void* d_out, int out_size) {
    const float* features = (const float*)d_in[0];
    const int* rois = (const int*)d_in[1];
    const float* w1 = (const float*)d_in[2];
    const float* b1 = (const float*)d_in[3];
    const float* w2 = (const float*)d_in[4];
    const float* b2 = (const float*)d_in[5];
    const float* w_cls = (const float*)d_in[6];
    const float* b_cls = (const float*)d_in[7];
    const float* w_reg = (const float*)d_in[8];
    const float* b_reg = (const float*)d_in[9];
    float* out = (float*)d_out;

    void* p_Ahf;   cudaGetSymbolAddress(&p_Ahf, g_Ahf);
    void* p_Bhi;   cudaGetSymbolAddress(&p_Bhi, g_Bhi);
    void* p_Blo;   cudaGetSymbolAddress(&p_Blo, g_Blo);
    void* p_part1; cudaGetSymbolAddress(&p_part1, g_part1);
    void* p_h1hi;  cudaGetSymbolAddress(&p_h1hi, g_h1hi);
    void* p_h1lo;  cudaGetSymbolAddress(&p_h1lo, g_h1lo);
    void* p_B2hi;  cudaGetSymbolAddress(&p_B2hi, g_B2hi);
    void* p_B2lo;  cudaGetSymbolAddress(&p_B2lo, g_B2lo);
    void* p_part2; cudaGetSymbolAddress(&p_part2, g_part2);

    const int smem1 = NSTAGE * 51200;  // 153600
    const int smem2 = NSTAGE * 61440;  // 184320
    cudaFuncSetAttribute(k_hmma<false>, cudaFuncAttributeMaxDynamicSharedMemorySize, smem1);
    cudaFuncSetAttribute(k_hmma<true>, cudaFuncAttributeMaxDynamicSharedMemorySize, smem2);

    // 1) integral image (channel-innermost layout)
    k_xscan<<<dim3(HH, CCH / 32), 1024>>>(features);
    k_yscan<<<((WW + 1) * (CCH / 4) + 255) / 256, 256>>>();

    // 2) ROI pooling -> fp16 A matrix
    k_pool<<<NROI, CCH>>>(rois);

    // 3) weight prep (fp16 hi/lo)
    k_prep_w1<<<dim3(POOLP * POOLP, CCH / 32, FF / 32), dim3(32, 8)>>>(w1);
    k_prep_w2<<<dim3(FF / 32, FF / 32), dim3(32, 8)>>>(w2);

    // 4) GEMM1 on HMMA (fp16 2-term, BN=256, split-K=8) + reduce/bias/relu
    k_hmma<false><<<dim3((NROI + 127) / 128, 1, KSP), 512, smem1>>>(
        (const __half*)p_Ahf, (const __half*)p_Ahf,
        (const __half*)p_Bhi, (const __half*)p_Blo,
        (float*)p_part1, NROI, K1, SLICE1, NCHK1);
    k_reduce_hf<<<NROI, FF>>>((const float*)p_part1, b1);

    // 5) GEMM2 on HMMA (fp16 3-term, K=256) + bias/relu -> h2
    k_hmma<true><<<dim3((NROI + 127) / 128, 1, 1), 512, smem2>>>(
        (const __half*)p_h1hi, (const __half*)p_h1lo,
        (const __half*)p_B2hi, (const __half*)p_B2lo,
        (float*)p_part2, NROI, FF, FF, FF / 32);
    k_bias2<<<NROI, FF>>>((const float*)p_part2, b2);

    // 6) heads
    k_heads<<<NROI, 32>>>(w_cls, b_cls, w_reg, b_reg, out);

    (void)in_sizes; (void)n_in; (void)out_size;
}